// round 5
// baseline (speedup 1.0000x reference)
#include <cuda_runtime.h>
#include <cstdint>

#define NB 32
#define NA 8400
#define NC 80
#define KTOP 1024
#define NG 32
#define NSUP 16
#define MAX_DET 300
#define CONF_NMS 0.25f
#define IOU_NMS 0.45f
#define CONF_MATCH 0.5f
#define IOU_MATCH 0.6f
#define MAX_WH 7680.0f
#define SORT_N 16384

// ---------------- scratch (global __device__ arrays; no allocation) ----------------
__device__ float        g_conf[NB * NA];
__device__ int          g_cls[NB * NA];
__device__ float        g_boxes_k[NB * KTOP * 4];
__device__ float        g_conf_k[NB * KTOP];
__device__ int          g_cls_k[NB * KTOP];
__device__ unsigned char g_keep[NB * KTOP];

// ---------------- Kernel 1: decode conf = max over classes, cls = argmax -----------
__global__ void k_decode(const float* __restrict__ preds) {
    int t = blockIdx.x * blockDim.x + threadIdx.x;
    if (t >= NB * NA) return;
    int b = t / NA;
    int a = t - b * NA;
    const float* sc = preds + ((size_t)b * 84 + 4) * NA + a;
    float m = sc[0];
    int arg = 0;
#pragma unroll 4
    for (int c = 1; c < NC; c++) {
        float v = sc[(size_t)c * NA];
        if (v > m) { m = v; arg = c; }   // strict > keeps FIRST max (jnp.argmax semantics)
    }
    g_conf[t] = (m > CONF_NMS) ? m : 0.0f;
    g_cls[t]  = arg;
}

// ---------------- Kernel 2: exact stable top-K via bitonic sort of u64 keys --------
// key = (~float_bits(conf) << 32) | anchor_index  -> ascending sort gives
// descending conf with ascending index tie-break (matches lax.top_k).
__global__ void k_topk(const float* __restrict__ preds) {
    extern __shared__ unsigned long long skey[];
    const int b = blockIdx.x;
    const int tid = threadIdx.x;
    const int T = 1024;

    for (int i = tid; i < SORT_N; i += T) {
        unsigned long long key;
        if (i < NA) {
            float c = g_conf[b * NA + i];
            unsigned fb = __float_as_uint(c);   // conf >= 0, bits monotone
            key = ((unsigned long long)(~fb) << 32) | (unsigned)i;
        } else {
            key = ~0ULL;   // padding sorts last
        }
        skey[i] = key;
    }
    __syncthreads();

    for (unsigned k = 2; k <= SORT_N; k <<= 1) {
        for (unsigned j = k >> 1; j > 0; j >>= 1) {
#pragma unroll 1
            for (unsigned i = tid; i < SORT_N; i += T) {
                unsigned ixj = i ^ j;
                if (ixj > i) {
                    unsigned long long x = skey[i];
                    unsigned long long y = skey[ixj];
                    bool up = ((i & k) == 0);
                    if (up ? (x > y) : (x < y)) { skey[i] = y; skey[ixj] = x; }
                }
            }
            __syncthreads();
        }
    }

    // gather top-KTOP: decode conf bits exactly, fetch box + cls
    {
        unsigned long long key = skey[tid];
        unsigned fb = ~(unsigned)(key >> 32);
        float conf = __uint_as_float(fb);
        int a = (int)(key & 0xFFFFFFFFu);
        float cx = preds[((size_t)b * 84 + 0) * NA + a];
        float cy = preds[((size_t)b * 84 + 1) * NA + a];
        float w  = preds[((size_t)b * 84 + 2) * NA + a];
        float h  = preds[((size_t)b * 84 + 3) * NA + a];
        int o = b * KTOP + tid;
        g_boxes_k[o * 4 + 0] = cx - w * 0.5f;
        g_boxes_k[o * 4 + 1] = cy - h * 0.5f;
        g_boxes_k[o * 4 + 2] = cx + w * 0.5f;
        g_boxes_k[o * 4 + 3] = cy + h * 0.5f;
        g_conf_k[o] = conf;
        g_cls_k[o]  = g_cls[b * NA + a];
    }
}

// ---------------- Kernel 3: bitmask greedy NMS (class-shifted boxes) ----------------
// dyn smem: float4 sbox[1024] (16384B) | u64 mask[1024*16] (131072B) | u8 valid[1024]
__global__ void k_nms() {
    extern __shared__ char smem[];
    float4* sbox = (float4*)smem;
    unsigned long long* mask = (unsigned long long*)(smem + 16384);
    unsigned char* sval = (unsigned char*)(smem + 16384 + 131072);

    const int b = blockIdx.x;
    const int i = threadIdx.x;
    const int o = b * KTOP + i;

    float4 bx;
    bx.x = g_boxes_k[o * 4 + 0];
    bx.y = g_boxes_k[o * 4 + 1];
    bx.z = g_boxes_k[o * 4 + 2];
    bx.w = g_boxes_k[o * 4 + 3];
    float shift = (float)g_cls_k[o] * MAX_WH;
    bx.x += shift; bx.y += shift; bx.z += shift; bx.w += shift;
    sbox[i] = bx;
    sval[i] = (g_conf_k[o] > 0.0f) ? 1 : 0;
    __syncthreads();

    float area_i = (bx.z - bx.x) * (bx.w - bx.y);
#pragma unroll 1
    for (int w = 0; w < 16; w++) {
        unsigned long long m = 0;
#pragma unroll 8
        for (int t = 0; t < 64; t++) {
            int j = w * 64 + t;
            float4 bj = sbox[j];
            float lx = fmaxf(bx.x, bj.x);
            float ly = fmaxf(bx.y, bj.y);
            float rx = fminf(bx.z, bj.z);
            float ry = fminf(bx.w, bj.w);
            float iw = fmaxf(rx - lx, 0.0f);
            float ih = fmaxf(ry - ly, 0.0f);
            float inter = iw * ih;
            float area_j = (bj.z - bj.x) * (bj.w - bj.y);
            float iou = inter / (area_i + area_j - inter + 1e-9f);
            m |= ((unsigned long long)(iou > IOU_NMS)) << t;
        }
        mask[i * 16 + w] = m;
    }
    __syncthreads();

    // warp-serial resolve: lanes 0..15 each own one 64-bit remv word
    if (threadIdx.x < 16) {
        const int lane = threadIdx.x;
        unsigned long long remv = 0;
        int cnt = 0;
        for (int ii = 0; ii < KTOP; ii++) {
            int w = ii >> 6, bbit = ii & 63;
            unsigned long long mrow = mask[ii * 16 + lane];  // prefetchable, independent
            int sup = 0;
            if (lane == w) sup = (int)((remv >> bbit) & 1ULL);
            sup = __shfl_sync(0x0000FFFFu, sup, w);
            int keep = (sval[ii] != 0) && !sup;
            if (keep) remv |= mrow;
            if (lane == 0) {
                if (keep) cnt++;
                g_keep[b * KTOP + ii] = (unsigned char)(keep && cnt <= MAX_DET);
            }
        }
    }
}

// ---------------- Kernel 4: GT matching + stats (one block per batch) --------------
__global__ void k_match(const float* __restrict__ gt_boxes,
                        const int* __restrict__ gt_cls,
                        const void* __restrict__ gt_mask_raw,
                        const int* __restrict__ cat_to_super,
                        float* __restrict__ out) {
    __shared__ float4 sbox[KTOP];
    __shared__ float  sconf[KTOP];
    __shared__ int    scls[KTOP];
    __shared__ unsigned char spv[KTOP];
    __shared__ float  s_biou[NG];
    __shared__ float  s_bconf[NG];
    __shared__ int    s_hit[NG];
    __shared__ int    s_gm[NG];
    __shared__ float  cat_counts[NC];
    __shared__ float  sup_counts[NSUP];
    __shared__ int    s_npred;
    __shared__ int    s_is_u8;   // gt_mask dtype detection

    const int b = blockIdx.x;
    const int tid = threadIdx.x;
    const int o = b * KTOP + tid;

    if (tid == 0) { s_npred = 0; s_is_u8 = 0; }
    if (tid < NC)   cat_counts[tid] = 0.0f;
    if (tid < NSUP) sup_counts[tid] = 0.0f;
    __syncthreads();

    // dtype probe: int32 0/1 little-endian => all bytes at offset%4!=0 are zero.
    const unsigned char* mb = (const unsigned char*)gt_mask_raw;
    if ((tid & 3) != 0 && mb[tid] != 0) atomicOr(&s_is_u8, 1);

    float4 bx;
    bx.x = g_boxes_k[o * 4 + 0];
    bx.y = g_boxes_k[o * 4 + 1];
    bx.z = g_boxes_k[o * 4 + 2];
    bx.w = g_boxes_k[o * 4 + 3];
    sbox[tid] = bx;
    float cf = g_conf_k[o];
    sconf[tid] = cf;
    scls[tid] = g_cls_k[o];
    int pv = (g_keep[o] != 0) && (cf > CONF_MATCH);
    spv[tid] = (unsigned char)pv;
    __syncthreads();

    unsigned bal = __ballot_sync(0xFFFFFFFFu, pv);
    if ((tid & 31) == 0) atomicAdd(&s_npred, __popc(bal));

    const int g = tid >> 5;
    const int lane = tid & 31;
    float gx1 = gt_boxes[((size_t)b * NG + g) * 4 + 0];
    float gy1 = gt_boxes[((size_t)b * NG + g) * 4 + 1];
    float gx2 = gt_boxes[((size_t)b * NG + g) * 4 + 2];
    float gy2 = gt_boxes[((size_t)b * NG + g) * 4 + 3];
    int gc = gt_cls[b * NG + g];
    float garea = (gx2 - gx1) * (gy2 - gy1);

    float best = -1.0f;
    int bidx = 0;
#pragma unroll 4
    for (int t = 0; t < KTOP / 32; t++) {
        int i = t * 32 + lane;
        float v = -1.0f;
        if (spv[i] && scls[i] == gc) {
            float4 p = sbox[i];
            float lx = fmaxf(p.x, gx1);
            float ly = fmaxf(p.y, gy1);
            float rx = fminf(p.z, gx2);
            float ry = fminf(p.w, gy2);
            float iw = fmaxf(rx - lx, 0.0f);
            float ih = fmaxf(ry - ly, 0.0f);
            float inter = iw * ih;
            float pa = (p.z - p.x) * (p.w - p.y);
            v = inter / (pa + garea - inter + 1e-9f);
        }
        if (v > best) { best = v; bidx = i; }   // ascending i per lane -> first max
    }
    // warp reduce max with lowest-index tie-break
    for (int off = 16; off > 0; off >>= 1) {
        float ob = __shfl_down_sync(0xFFFFFFFFu, best, off);
        int   oi = __shfl_down_sync(0xFFFFFFFFu, bidx, off);
        if (ob > best || (ob == best && oi < bidx)) { best = ob; bidx = oi; }
    }
    __syncthreads();   // ensure s_is_u8 probe complete before use
    if (lane == 0) {
        int gm;
        if (s_is_u8) gm = (mb[b * NG + g] != 0);
        else         gm = (((const int*)gt_mask_raw)[b * NG + g] != 0);
        s_biou[g]  = best;
        s_bconf[g] = sconf[bidx];
        int hit = (best > IOU_MATCH) && gm;
        s_hit[g] = hit;
        s_gm[g]  = gm;
        if (gm) {
            atomicAdd(&cat_counts[gc], 1.0f);
            atomicAdd(&sup_counts[cat_to_super[gc]], 1.0f);
        }
    }
    __syncthreads();

    if (tid < 32) {
        int gmv = s_gm[tid], hitv = s_hit[tid];
        float si = hitv ? s_biou[tid]  : 0.0f;
        float sc = hitv ? s_bconf[tid] : 0.0f;
        int n_gt = gmv, n_hit = hitv;
        float sum_iou = si, sum_conf = sc;
        for (int off = 16; off > 0; off >>= 1) {
            n_gt    += __shfl_down_sync(0xFFFFFFFFu, n_gt, off);
            n_hit   += __shfl_down_sync(0xFFFFFFFFu, n_hit, off);
            sum_iou  += __shfl_down_sync(0xFFFFFFFFu, sum_iou, off);
            sum_conf += __shfl_down_sync(0xFFFFFFFFu, sum_conf, off);
        }
        if (tid == 0) {
            float fh = (float)n_hit;
            float mean_iou  = sum_iou / fmaxf(fh, 1.0f);
            float mean_conf = (n_hit > 0) ? (sum_conf / fmaxf(fh, 1.0f)) : 1.0f;
            float correct   = fh / fmaxf((float)n_gt, 1.0f);
            float bc = cat_counts[0]; int mfc = 0;
            for (int c = 1; c < NC; c++)
                if (cat_counts[c] > bc) { bc = cat_counts[c]; mfc = c; }   // first-max
            float bs = sup_counts[0]; int mfs = 0;
            for (int s = 1; s < NSUP; s++)
                if (sup_counts[s] > bs) { bs = sup_counts[s]; mfs = s; }
            float r0, r1, r2, r3, r4;
            if (n_gt == 0) {
                if (s_npred == 0) { r0 = 1.0f; r1 = 1.0f; r2 = -1.0f; r3 = -1.0f; r4 = 1.0f; }
                else              { r0 = 0.0f; r1 = 1.0f; r2 = -2.0f; r3 = -2.0f; r4 = 0.0f; }
            } else {
                r0 = mean_iou; r1 = mean_conf; r2 = (float)mfc; r3 = (float)mfs; r4 = correct;
            }
            out[b * 5 + 0] = r0;
            out[b * 5 + 1] = r1;
            out[b * 5 + 2] = r2;
            out[b * 5 + 3] = r3;
            out[b * 5 + 4] = r4;
        }
    }
}

// ---------------- launch -----------------------------------------------------------
extern "C" void kernel_launch(void* const* d_in, const int* in_sizes, int n_in,
                              void* d_out, int out_size) {
    const float* preds        = (const float*)d_in[0];
    const float* gt_boxes     = (const float*)d_in[1];
    const int*   gt_cls       = (const int*)d_in[2];
    const void*  gt_mask      = (const void*)d_in[3];
    const int*   cat_to_super = (const int*)d_in[4];
    float* out = (float*)d_out;

    (void)in_sizes; (void)n_in; (void)out_size;

    cudaFuncSetAttribute(k_topk, cudaFuncAttributeMaxDynamicSharedMemorySize,
                         SORT_N * (int)sizeof(unsigned long long));
    const int nms_smem = 16384 + 131072 + 1024;
    cudaFuncSetAttribute(k_nms, cudaFuncAttributeMaxDynamicSharedMemorySize, nms_smem);

    k_decode<<<(NB * NA + 255) / 256, 256>>>(preds);
    k_topk<<<NB, 1024, SORT_N * sizeof(unsigned long long)>>>(preds);
    k_nms<<<NB, 1024, nms_smem>>>();
    k_match<<<NB, 1024>>>(gt_boxes, gt_cls, gt_mask, cat_to_super, out);
}

// round 7
// speedup vs baseline: 2.7742x; 2.7742x over previous
#include <cuda_runtime.h>
#include <cstdint>

typedef unsigned long long ull;

#define NB 32
#define NA 8400
#define NC 80
#define KTOP 1024
#define NG 32
#define NSUP 16
#define MAX_DET 300
#define CONF_NMS 0.25f
#define IOU_NMS 0.45f
#define CONF_MATCH 0.5f
#define IOU_MATCH 0.6f
#define MAX_WH 7680.0f

// histogram select parameters: bucket = 1 + ((fb - 0x3E800000) >> 11), monotone in conf
#define FB_BASE 0x3E800000u
#define BSHIFT 11
#define NBPAD 9216          // 1024 threads * CH chunks, covers 8193 buckets
#define CH 9
#define CAP 2048            // gather capacity / sort size (expected ~1100)

// ---------------- scratch (global __device__ arrays; no allocation) ----------------
__device__ unsigned               g_hist[NB * NBPAD];
__device__ __align__(16) float    g_conf[NB * NA];
__device__ __align__(16) int      g_cls[NB * NA];
__device__ float4                 g_box4[NB * KTOP];    // unshifted x1y1x2y2
__device__ float4                 g_sbox4[NB * KTOP];   // class-shifted
__device__ float                  g_area[NB * KTOP];    // area of shifted box
__device__ float                  g_conf_k[NB * KTOP];
__device__ int                    g_cls_k[NB * KTOP];
__device__ __align__(16) ull      g_mask[NB * KTOP * 16];

__device__ __forceinline__ int conf_bucket(float c) {
    if (c <= 0.0f) return 0;
    unsigned fb = __float_as_uint(c);
    return 1 + (int)((fb - FB_BASE) >> BSHIFT);
}

// ---------------- Kernel 0: zero histograms (graph replays re-run everything) ------
__global__ void k_zero() {
    int t = blockIdx.x * blockDim.x + threadIdx.x;
    if (t < NB * NBPAD) g_hist[t] = 0u;
}

// ---------------- Kernel 1: decode conf/cls (vectorized x4) + histogram ------------
__global__ void k_decode(const float* __restrict__ preds) {
    int t = blockIdx.x * blockDim.x + threadIdx.x;
    if (t >= NB * (NA / 4)) return;
    int b = t / (NA / 4);
    int a4 = (t - b * (NA / 4)) * 4;
    const float* base = preds + (size_t)b * 84 * NA;

    float4 m = *(const float4*)(base + (size_t)4 * NA + a4);
    int ax = 0, ay = 0, az = 0, aw = 0;
#pragma unroll 4
    for (int c = 1; c < NC; c++) {
        float4 v = *(const float4*)(base + (size_t)(4 + c) * NA + a4);
        if (v.x > m.x) { m.x = v.x; ax = c; }   // strict > keeps FIRST max
        if (v.y > m.y) { m.y = v.y; ay = c; }
        if (v.z > m.z) { m.z = v.z; az = c; }
        if (v.w > m.w) { m.w = v.w; aw = c; }
    }
    m.x = (m.x > CONF_NMS) ? m.x : 0.0f;
    m.y = (m.y > CONF_NMS) ? m.y : 0.0f;
    m.z = (m.z > CONF_NMS) ? m.z : 0.0f;
    m.w = (m.w > CONF_NMS) ? m.w : 0.0f;

    *(float4*)&g_conf[b * NA + a4] = m;
    *(int4*)&g_cls[b * NA + a4] = make_int4(ax, ay, az, aw);

    unsigned* h = &g_hist[b * NBPAD];
    atomicAdd(&h[conf_bucket(m.x)], 1u);
    atomicAdd(&h[conf_bucket(m.y)], 1u);
    atomicAdd(&h[conf_bucket(m.z)], 1u);
    atomicAdd(&h[conf_bucket(m.w)], 1u);
}

// ---------------- Kernel 2: histogram select + bitonic sort of <=2048 candidates ---
// keys = (~float_bits(conf) << 32) | index : ascending sort == conf desc, idx asc
// (identical ordering to lax.top_k incl. ties)
__global__ __launch_bounds__(1024, 1) void k_select(const float* __restrict__ preds) {
    extern __shared__ ull skey[];               // CAP entries
    __shared__ unsigned s_suf[1024];
    __shared__ int s_bstar;
    __shared__ int s_cnt;

    const int b = blockIdx.x;
    const int tid = threadIdx.x;
    const int q0 = tid * CH;

    // chunk sums
    unsigned v = 0;
#pragma unroll
    for (int k = 0; k < CH; k++) v += g_hist[b * NBPAD + q0 + k];
    s_suf[tid] = v;
    __syncthreads();
    // inclusive suffix scan (Hillis-Steele)
    for (int d = 1; d < 1024; d <<= 1) {
        unsigned add = (tid + d < 1024) ? s_suf[tid + d] : 0u;
        __syncthreads();
        v += add;
        s_suf[tid] = v;
        __syncthreads();
    }
    // unique crossing thread finds threshold bucket B*: largest bucket with
    // count(buckets >= B*) >= KTOP
    unsigned nxt = (tid < 1023) ? s_suf[tid + 1] : 0u;
    if (s_suf[tid] >= KTOP && !(tid < 1023 && nxt >= KTOP)) {
        unsigned running = nxt;
        int B = q0;
        for (int q = q0 + CH - 1; q >= q0; q--) {
            running += g_hist[b * NBPAD + q];
            if (running >= KTOP) { B = q; break; }
        }
        s_bstar = B;
    }
    if (tid == 0) s_cnt = 0;
    for (int i = tid; i < CAP; i += 1024) skey[i] = ~0ULL;   // padding sorts last
    __syncthreads();

    const int Bs = s_bstar;
    for (int i = tid; i < NA; i += 1024) {
        float c = g_conf[b * NA + i];
        if (conf_bucket(c) >= Bs) {
            int p = atomicAdd(&s_cnt, 1);
            if (p < CAP)
                skey[p] = ((ull)(~__float_as_uint(c)) << 32) | (unsigned)i;
        }
    }
    __syncthreads();

    // bitonic sort of CAP keys
    for (unsigned k = 2; k <= CAP; k <<= 1) {
        for (unsigned j = k >> 1; j > 0; j >>= 1) {
#pragma unroll 1
            for (unsigned i = tid; i < CAP; i += 1024) {
                unsigned ixj = i ^ j;
                if (ixj > i) {
                    ull x = skey[i];
                    ull y = skey[ixj];
                    bool up = ((i & k) == 0);
                    if (up ? (x > y) : (x < y)) { skey[i] = y; skey[ixj] = x; }
                }
            }
            __syncthreads();
        }
    }

    // emit top-KTOP (guaranteed >= KTOP gathered)
    ull key = skey[tid];
    unsigned fb = ~(unsigned)(key >> 32);
    float conf = __uint_as_float(fb);
    int a = (int)(key & 0xFFFFFFFFu);
    const float* base = preds + (size_t)b * 84 * NA;
    float cx = base[a];
    float cy = base[NA + a];
    float w  = base[2 * NA + a];
    float h  = base[3 * NA + a];
    float x1 = cx - w * 0.5f, y1 = cy - h * 0.5f;
    float x2 = cx + w * 0.5f, y2 = cy + h * 0.5f;
    int o = b * KTOP + tid;
    int cls = g_cls[b * NA + a];
    float sh = (float)cls * MAX_WH;
    float sx1 = x1 + sh, sy1 = y1 + sh, sx2 = x2 + sh, sy2 = y2 + sh;
    g_box4[o]  = make_float4(x1, y1, x2, y2);
    g_sbox4[o] = make_float4(sx1, sy1, sx2, sy2);
    g_area[o]  = (sx2 - sx1) * (sy2 - sy1);     // area AFTER shift (bit-matches ref)
    g_conf_k[o] = conf;
    g_cls_k[o]  = cls;
}

// ---------------- Kernel 3: NMS IoU bit-mask, spread across the chip ----------------
// grid (16, NB): block computes 64 rows x 1024 cols of the mask
__global__ __launch_bounds__(1024, 1) void k_nmsmask() {
    __shared__ float4 sb[KTOP];
    __shared__ float  sa[KTOP];
    const int b = blockIdx.y;
    const int tid = threadIdx.x;
    sb[tid] = g_sbox4[b * KTOP + tid];
    sa[tid] = g_area[b * KTOP + tid];
    __syncthreads();

    const int row = blockIdx.x * 64 + (tid >> 4);
    const int w = tid & 15;
    float4 bi = sb[row];
    float ai = sa[row];
    ull m = 0;
#pragma unroll 16
    for (int t2 = 0; t2 < 64; t2++) {
        int jj = (t2 + w) & 63;           // rotate to avoid smem bank conflicts
        int j = w * 64 + jj;
        float4 bj = sb[j];
        float lx = fmaxf(bi.x, bj.x);
        float ly = fmaxf(bi.y, bj.y);
        float rx = fminf(bi.z, bj.z);
        float ry = fminf(bi.w, bj.w);
        float iw = fmaxf(rx - lx, 0.0f);
        float ih = fmaxf(ry - ly, 0.0f);
        float inter = iw * ih;
        float iou = inter / (ai + sa[j] - inter + 1e-9f);   // same arithmetic as R1
        m |= ((ull)(iou > IOU_NMS)) << jj;
    }
    g_mask[((size_t)b * KTOP + row) * 16 + w] = m;
}

// ---------------- Kernel 4: grouped NMS resolve + GT match (fused) ------------------
__global__ __launch_bounds__(1024, 1) void k_resolve_match(
        const float* __restrict__ gt_boxes,
        const int* __restrict__ gt_cls,
        const void* __restrict__ gt_mask_raw,
        const int* __restrict__ cat_to_super,
        float* __restrict__ out) {
    extern __shared__ char dyn[];
    ull* smask = (ull*)dyn;                   // KTOP*16 u64 = 128 KB

    __shared__ float4 sbox[KTOP];
    __shared__ float  sconf[KTOP];
    __shared__ int    scls[KTOP];
    __shared__ unsigned char sval[KTOP];
    __shared__ unsigned char spv[KTOP];
    __shared__ ull    s_k64[16];
    __shared__ int    s_base[17];
    __shared__ float  s_biou[NG];
    __shared__ float  s_bconf[NG];
    __shared__ int    s_hit[NG];
    __shared__ int    s_gm[NG];
    __shared__ float  cat_counts[NC];
    __shared__ float  sup_counts[NSUP];
    __shared__ int    s_npred;
    __shared__ int    s_is_u8;

    const int b = blockIdx.x;
    const int tid = threadIdx.x;
    const int o = b * KTOP + tid;

    // bulk copy mask batch-slice into smem (8 x float4 per thread, coalesced)
    const float4* msrc = (const float4*)(g_mask + (size_t)b * KTOP * 16);
    float4* mdst = (float4*)smask;
#pragma unroll
    for (int i = 0; i < 8; i++) mdst[tid + i * 1024] = msrc[tid + i * 1024];

    float cf = g_conf_k[o];
    sbox[tid]  = g_box4[o];
    sconf[tid] = cf;
    scls[tid]  = g_cls_k[o];
    sval[tid]  = (cf > 0.0f) ? 1 : 0;
    if (tid == 0) { s_npred = 0; s_is_u8 = 0; }
    if (tid < NC)   cat_counts[tid] = 0.0f;
    if (tid < NSUP) sup_counts[tid] = 0.0f;
    // gt_mask dtype probe: int32 0/1 LE => bytes at offset%4!=0 are all zero
    const unsigned char* mb = (const unsigned char*)gt_mask_raw;
    if ((tid & 3) != 0 && mb[tid] != 0) atomicOr(&s_is_u8, 1);
    __syncthreads();

    // ---- grouped greedy resolve: lanes 0..15 each own one 64-bit remv word ----
    if (tid < 16) {
        const int lane = tid;
        ull remv = 0;
        for (int g = 0; g < 16; g++) {
            ull k64 = 0;
            if (lane == g) {
                // local serial resolve of this word's 64 candidates;
                // mask rows (own word) software-prefetched 8 ahead
                ull buf[8];
#pragma unroll
                for (int t = 0; t < 8; t++) buf[t] = smask[(size_t)(g * 64 + t) * 16 + g];
#pragma unroll
                for (int t = 0; t < 64; t++) {
                    ull mrow = buf[t & 7];
                    if (t < 56) buf[t & 7] = smask[(size_t)(g * 64 + t + 8) * 16 + g];
                    if (sval[g * 64 + t] && !((remv >> t) & 1ULL)) {
                        remv |= mrow;
                        k64 |= (1ULL << t);
                    }
                }
            }
            k64 = __shfl_sync(0x0000FFFFu, k64, g);
            if (lane != g) {
                ull kk = k64;
                while (kk) {
                    int t = __ffsll(kk) - 1;
                    kk &= kk - 1;
                    remv |= smask[(size_t)(g * 64 + t) * 16 + lane];
                }
            }
            if (lane == 0) s_k64[g] = k64;
        }
    }
    __syncthreads();
    if (tid == 0) {
        int r = 0;
        for (int w = 0; w < 16; w++) { s_base[w] = r; r += __popcll(s_k64[w]); }
        s_base[16] = r;
    }
    __syncthreads();
    {
        int w = tid >> 6, t = tid & 63;
        ull kw = s_k64[w];
        int kp = (int)((kw >> t) & 1ULL);
        ull pmask = (t == 63) ? ~0ULL : ((1ULL << (t + 1)) - 1ULL);
        int rank = s_base[w] + __popcll(kw & pmask);     // inclusive cumsum
        int keep = kp && (rank <= MAX_DET);
        int pv = keep && (sconf[tid] > CONF_MATCH);
        spv[tid] = (unsigned char)pv;
        unsigned bal = __ballot_sync(0xFFFFFFFFu, pv);
        if ((tid & 31) == 0) atomicAdd(&s_npred, __popc(bal));
    }
    __syncthreads();

    // ---- GT matching (one warp per GT) ----
    const int g = tid >> 5;
    const int lane = tid & 31;
    const float4 gb = *(const float4*)(gt_boxes + ((size_t)b * NG + g) * 4);
    const int gc = gt_cls[b * NG + g];
    const float garea = (gb.z - gb.x) * (gb.w - gb.y);

    float best = -1.0f;
    int bidx = 0;
#pragma unroll 4
    for (int t = 0; t < KTOP / 32; t++) {
        int i = t * 32 + lane;
        float v = -1.0f;
        if (spv[i] && scls[i] == gc) {
            float4 p = sbox[i];
            float lx = fmaxf(p.x, gb.x);
            float ly = fmaxf(p.y, gb.y);
            float rx = fminf(p.z, gb.z);
            float ry = fminf(p.w, gb.w);
            float iw = fmaxf(rx - lx, 0.0f);
            float ih = fmaxf(ry - ly, 0.0f);
            float inter = iw * ih;
            float pa = (p.z - p.x) * (p.w - p.y);
            v = inter / (pa + garea - inter + 1e-9f);
        }
        if (v > best) { best = v; bidx = i; }   // ascending i per lane -> first max
    }
    for (int off = 16; off > 0; off >>= 1) {
        float ob = __shfl_down_sync(0xFFFFFFFFu, best, off);
        int   oi = __shfl_down_sync(0xFFFFFFFFu, bidx, off);
        if (ob > best || (ob == best && oi < bidx)) { best = ob; bidx = oi; }
    }
    if (lane == 0) {
        int gm;
        if (s_is_u8) gm = (mb[b * NG + g] != 0);
        else         gm = (((const int*)gt_mask_raw)[b * NG + g] != 0);
        s_biou[g]  = best;
        s_bconf[g] = sconf[bidx];
        int hit = (best > IOU_MATCH) && gm;
        s_hit[g] = hit;
        s_gm[g]  = gm;
        if (gm) {
            atomicAdd(&cat_counts[gc], 1.0f);
            atomicAdd(&sup_counts[cat_to_super[gc]], 1.0f);
        }
    }
    __syncthreads();

    if (tid < 32) {
        int gmv = s_gm[tid], hitv = s_hit[tid];
        float si = hitv ? s_biou[tid]  : 0.0f;
        float sc = hitv ? s_bconf[tid] : 0.0f;
        int n_gt = gmv, n_hit = hitv;
        float sum_iou = si, sum_conf = sc;
        for (int off = 16; off > 0; off >>= 1) {
            n_gt     += __shfl_down_sync(0xFFFFFFFFu, n_gt, off);
            n_hit    += __shfl_down_sync(0xFFFFFFFFu, n_hit, off);
            sum_iou  += __shfl_down_sync(0xFFFFFFFFu, sum_iou, off);
            sum_conf += __shfl_down_sync(0xFFFFFFFFu, sum_conf, off);
        }
        if (tid == 0) {
            float fh = (float)n_hit;
            float mean_iou  = sum_iou / fmaxf(fh, 1.0f);
            float mean_conf = (n_hit > 0) ? (sum_conf / fmaxf(fh, 1.0f)) : 1.0f;
            float correct   = fh / fmaxf((float)n_gt, 1.0f);
            float bc = cat_counts[0]; int mfc = 0;
            for (int c = 1; c < NC; c++)
                if (cat_counts[c] > bc) { bc = cat_counts[c]; mfc = c; }
            float bs = sup_counts[0]; int mfs = 0;
            for (int s = 1; s < NSUP; s++)
                if (sup_counts[s] > bs) { bs = sup_counts[s]; mfs = s; }
            float r0, r1, r2, r3, r4;
            if (n_gt == 0) {
                if (s_npred == 0) { r0 = 1.0f; r1 = 1.0f; r2 = -1.0f; r3 = -1.0f; r4 = 1.0f; }
                else              { r0 = 0.0f; r1 = 1.0f; r2 = -2.0f; r3 = -2.0f; r4 = 0.0f; }
            } else {
                r0 = mean_iou; r1 = mean_conf; r2 = (float)mfc; r3 = (float)mfs; r4 = correct;
            }
            out[b * 5 + 0] = r0;
            out[b * 5 + 1] = r1;
            out[b * 5 + 2] = r2;
            out[b * 5 + 3] = r3;
            out[b * 5 + 4] = r4;
        }
    }
}

// ---------------- launch -----------------------------------------------------------
extern "C" void kernel_launch(void* const* d_in, const int* in_sizes, int n_in,
                              void* d_out, int out_size) {
    const float* preds        = (const float*)d_in[0];
    const float* gt_boxes     = (const float*)d_in[1];
    const int*   gt_cls       = (const int*)d_in[2];
    const void*  gt_mask      = (const void*)d_in[3];
    const int*   cat_to_super = (const int*)d_in[4];
    float* out = (float*)d_out;

    (void)in_sizes; (void)n_in; (void)out_size;

    cudaFuncSetAttribute(k_resolve_match,
                         cudaFuncAttributeMaxDynamicSharedMemorySize,
                         KTOP * 16 * (int)sizeof(ull));

    k_zero<<<(NB * NBPAD + 1023) / 1024, 1024>>>();
    k_decode<<<(NB * (NA / 4) + 255) / 256, 256>>>(preds);
    k_select<<<NB, 1024, CAP * sizeof(ull)>>>(preds);
    k_nmsmask<<<dim3(16, NB), 1024>>>();
    k_resolve_match<<<NB, 1024, KTOP * 16 * sizeof(ull)>>>(gt_boxes, gt_cls, gt_mask,
                                                           cat_to_super, out);
}